// round 13
// baseline (speedup 1.0000x reference)
#include <cuda_runtime.h>
#include <cstdint>

// NCA: x[8,20,256,256], W1[128,60], b1[128], W2[20,128], steps=64
// tf32 mma.sync; 32x8 tile, 2 GEMM passes; smem-routed coalesced writeout.

#define BB 8
#define CC 20
#define HH 256
#define WW 256
#define KH 128

#define TILE_W 32
#define TILE_H 8
#define NTHREADS 128
#define NTILES 2048          // 8 x 32 x 8
#define GRID_BLOCKS 444      // 3 per SM

#define XS_ROWS 10
#define NPOS (XS_ROWS*34)          // 340
#define XS_ELEMS (CC*NPOS)         // 6800 floats
#define P_STRIDE 72                // u32; pair layout
#define DX_STRIDE 21

#define P_OFF  6800                          // float offset
#define DX_OFF (P_OFF + 128*P_STRIDE)        // 16016
#define SMEM_FLOATS (DX_OFF + 128*DX_STRIDE) // 18704
#define SMEM_BYTES (SMEM_FLOATS*4)           // 74816 B -> 3 blocks/SM

__device__ float g_bufA[BB*CC*HH*WW];
__device__ float g_bufB[BB*CC*HH*WW];
__device__ uint4 g_w1frag[16][4][32];   // [nt][kpair][lane]
__device__ uint4 g_w2frag[16][2][32];   // [nt][half][lane]

__device__ __forceinline__ uint32_t tf32r(float f) {
    uint32_t r;
    asm("cvt.rna.tf32.f32 %0, %1;" : "=r"(r) : "f"(f));
    return r;
}

__device__ __forceinline__ void mma8(float* c, const uint32_t* a,
                                     uint32_t b0, uint32_t b1) {
    asm volatile(
        "mma.sync.aligned.m16n8k8.row.col.f32.tf32.tf32.f32 "
        "{%0,%1,%2,%3}, {%4,%5,%6,%7}, {%8,%9}, {%0,%1,%2,%3};"
        : "+f"(c[0]), "+f"(c[1]), "+f"(c[2]), "+f"(c[3])
        : "r"(a[0]), "r"(a[1]), "r"(a[2]), "r"(a[3]), "r"(b0), "r"(b1));
}

__device__ __forceinline__ uint32_t rotl32(uint32_t v, int r) {
    return (v << r) | (v >> (32 - r));
}
// JAX threefry2x32 (20 rounds), bit-exact.
__device__ __forceinline__ void tf2x32(uint32_t k0, uint32_t k1,
                                       uint32_t& x0, uint32_t& x1) {
    uint32_t ks2 = k0 ^ k1 ^ 0x1BD11BDAu;
    x0 += k0; x1 += k1;
#define TFR(r) { x0 += x1; x1 = rotl32(x1, r); x1 ^= x0; }
    TFR(13) TFR(15) TFR(26) TFR(6)
    x0 += k1; x1 += ks2 + 1u;
    TFR(17) TFR(29) TFR(16) TFR(24)
    x0 += ks2; x1 += k0 + 2u;
    TFR(13) TFR(15) TFR(26) TFR(6)
    x0 += k0; x1 += k1 + 3u;
    TFR(17) TFR(29) TFR(16) TFR(24)
    x0 += k1; x1 += ks2 + 4u;
    TFR(13) TFR(15) TFR(26) TFR(6)
    x0 += ks2; x1 += k0 + 5u;
#undef TFR
}
__device__ __forceinline__ int refl(int v, int n) {
    v = (v < 0) ? -v : v;
    return (v >= n) ? (2 * n - 2 - v) : v;
}

// ---- prep: fragment-ordered weights (once per launch) ----
__global__ void prep_frags(const float* __restrict__ W1,
                           const float* __restrict__ b1,
                           const float* __restrict__ W2) {
    int i = blockIdx.x * blockDim.x + threadIdx.x;
    if (i < 16 * 4 * 32) {
        int nt = i >> 7, kp = (i >> 5) & 3, lane = i & 31;
        int g = lane >> 2, t = lane & 3;
        int row = nt * 8 + g;
        int c0 = (2 * kp) * 8 + t;
        uint4 q;
        q.x = (c0      < 60) ? tf32r(W1[row * 60 + c0])      : 0u;
        q.y = (c0 + 4  < 60) ? tf32r(W1[row * 60 + c0 + 4])  : 0u;
        q.z = (c0 + 8  < 60) ? tf32r(W1[row * 60 + c0 + 8])  : 0u;
        q.w = (c0 + 12 < 60) ? tf32r(W1[row * 60 + c0 + 12]) : 0u;
        g_w1frag[nt][kp][lane] = q;
    } else if (i < 16 * 4 * 32 + 16 * 2 * 32) {
        int j = i - 16 * 4 * 32;
        int nt = j >> 6, half = (j >> 5) & 1, lane = j & 31;
        int g = lane >> 2, t = lane & 3;
        int k = nt * 8 + t;
        uint4 q;
        if (half == 0) {
            int r0 = g, r1 = 8 + g;
            q.x = (r0 < 20) ? tf32r(W2[r0 * KH + k])     : 0u;
            q.y = (r0 < 20) ? tf32r(W2[r0 * KH + k + 4]) : 0u;
            q.z = (r1 < 20) ? tf32r(W2[r1 * KH + k])     : 0u;
            q.w = (r1 < 20) ? tf32r(W2[r1 * KH + k + 4]) : 0u;
        } else {
            int r2 = 16 + g;
            q.x = (r2 < 20) ? tf32r(W2[r2 * KH + k])     : 0u;
            q.y = (r2 < 20) ? tf32r(W2[r2 * KH + k + 4]) : 0u;
            q.z = __float_as_uint(b1[nt * 8 + 2 * t]);
            q.w = __float_as_uint(b1[nt * 8 + 2 * t + 1]);
        }
        g_w2frag[nt][half][lane] = q;
    }
}

__global__ void __launch_bounds__(NTHREADS, 3)
nca_step(const float* __restrict__ in, float* __restrict__ out, int step)
{
    extern __shared__ float smf[];
    float*    xs  = smf;                       // [20][10][34]
    uint32_t* Pu  = (uint32_t*)(smf + P_OFF);  // [128][72] tf32 pair layout
    float*    dxs = smf + DX_OFF;              // [128][21]

    const int tid  = threadIdx.x;
    const int w    = tid >> 5;
    const int lane = tid & 31;
    const int g = lane >> 2;
    const int t = lane & 3;

    uint32_t s0 = 0u, s1 = (uint32_t)step;
    tf2x32(0u, 42u, s0, s1);                  // fold_in(key(42), step)

    const int src  = (lane & ~3) | (t >> 1);
    const int src2 = src + 2;
    const int par  = t & 1;

    for (int tile = blockIdx.x; tile < NTILES; tile += GRID_BLOCKS) {
        const int ix = tile & 7;
        const int iy = (tile >> 3) & 31;
        const int bz = tile >> 8;
        const int bx0 = ix * TILE_W;
        const int by0 = iy * TILE_H;

        __syncthreads();   // xs reuse vs previous tile's readers

        // ---- stage xs: 1 div per spatial position, 20-ch pointer loop ----
        const float* inb = in + bz * (CC * HH * WW);
        for (int pp = tid; pp < NPOS; pp += NTHREADS) {
            int yy = pp / 34;
            int xx = pp - yy * 34;
            int gy = refl(by0 + yy - 1, HH);
            int gx = refl(bx0 + xx - 1, WW);
            const float* src_p = inb + (gy << 8) + gx;
            float* dst_p = xs + pp;
            #pragma unroll
            for (int c = 0; c < CC; c++)
                dst_p[c * NPOS] = src_p[c << 16];
        }
        __syncthreads();

        // ---- two GEMM passes over the 32x8 tile ----
        #pragma unroll 1
        for (int mo = 0; mo < 2; mo++) {
            const int yrow = mo * 4 + w;          // pixel y within tile

            // perceive own pixel -> P row (pair layout)
            {
                uint32_t pt[64];
                #pragma unroll
                for (int c = 0; c < CC; c++) {
                    const float* b = xs + (c * XS_ROWS + yrow) * 34 + lane;
                    float a00 = b[0],  a01 = b[1],  a02 = b[2];
                    float a10 = b[34], a11 = b[35], a12 = b[36];
                    float a20 = b[68], a21 = b[69], a22 = b[70];
                    pt[c]          = tf32r(a11);
                    pt[20 + 2 * c] = tf32r((a02 - a00 + 2.f * (a12 - a10) + a22 - a20) * 0.125f);
                    pt[21 + 2 * c] = tf32r((a20 - a00 + 2.f * (a21 - a01) + a22 - a02) * 0.125f);
                }
                pt[60] = pt[61] = pt[62] = pt[63] = 0u;
                uint4* prow = (uint4*)(Pu + tid * P_STRIDE);
                #pragma unroll
                for (int v = 0; v < 16; v++) {
                    int ks = v >> 1;
                    int tA = 2 * (v & 1);
                    prow[v] = make_uint4(pt[ks * 8 + tA],     pt[ks * 8 + tA + 4],
                                         pt[ks * 8 + tA + 1], pt[ks * 8 + tA + 5]);
                }
            }

            // fire flag for OWN pixel only
            bool fire_own;
            {
                int pidx = (bz << 16) + ((by0 + yrow) << 8) + (bx0 + lane);
                uint32_t r0 = 0u, r1 = (uint32_t)pidx;
                tf2x32(s0, s1, r0, r1);
                fire_own = ((r0 ^ r1) & 0x80000000u) == 0u;
            }
            __syncwarp();   // P rows (warp-local) visible

            // cache A fragments via LDS.64
            uint32_t afr[2][8][4];
            #pragma unroll
            for (int m = 0; m < 2; m++) {
                int r0 = (w * 32 + m * 16 + g) * P_STRIDE;
                int r1 = r0 + 8 * P_STRIDE;
                #pragma unroll
                for (int ks = 0; ks < 8; ks++) {
                    int o = 8 * ks + 2 * t;
                    uint2 lo = *(const uint2*)(Pu + r0 + o);
                    uint2 hi = *(const uint2*)(Pu + r1 + o);
                    afr[m][ks][0] = lo.x;
                    afr[m][ks][2] = lo.y;
                    afr[m][ks][1] = hi.x;
                    afr[m][ks][3] = hi.y;
                }
            }

            // fused GEMM1 -> relu -> shuffle -> GEMM2
            float acc2[2][3][4];
            #pragma unroll
            for (int m = 0; m < 2; m++)
                #pragma unroll
                for (int n = 0; n < 3; n++)
                    #pragma unroll
                    for (int j = 0; j < 4; j++) acc2[m][n][j] = 0.f;

            #pragma unroll 2
            for (int nt = 0; nt < 16; nt++) {
                uint32_t wb0[8], wb1[8];
                #pragma unroll
                for (int kp = 0; kp < 4; kp++) {
                    uint4 q = g_w1frag[nt][kp][lane];
                    wb0[2*kp]   = q.x;  wb1[2*kp]   = q.y;
                    wb0[2*kp+1] = q.z;  wb1[2*kp+1] = q.w;
                }
                uint4 v0 = g_w2frag[nt][0][lane];
                uint4 v1 = g_w2frag[nt][1][lane];
                float bc0 = __uint_as_float(v1.z);
                float bc1 = __uint_as_float(v1.w);

                #pragma unroll
                for (int m = 0; m < 2; m++) {
                    float ca[4] = {0.f, 0.f, 0.f, 0.f};
                    float cb[4] = {0.f, 0.f, 0.f, 0.f};
                    #pragma unroll
                    for (int ks = 0; ks < 4; ks++) {
                        mma8(ca, afr[m][ks],     wb0[ks],     wb1[ks]);
                        mma8(cb, afr[m][ks + 4], wb0[ks + 4], wb1[ks + 4]);
                    }
                    // raw f32 bits: tf32 MMA reads top 19 bits (RZ truncation)
                    uint32_t h0 = __float_as_uint(fmaxf(ca[0] + cb[0] + bc0, 0.f));
                    uint32_t h1 = __float_as_uint(fmaxf(ca[1] + cb[1] + bc1, 0.f));
                    uint32_t h2 = __float_as_uint(fmaxf(ca[2] + cb[2] + bc0, 0.f));
                    uint32_t h3 = __float_as_uint(fmaxf(ca[3] + cb[3] + bc1, 0.f));

                    uint32_t a[4];
                    uint32_t e, o;
                    e = __shfl_sync(0xffffffffu, h0, src);
                    o = __shfl_sync(0xffffffffu, h1, src);
                    a[0] = par ? o : e;
                    e = __shfl_sync(0xffffffffu, h2, src);
                    o = __shfl_sync(0xffffffffu, h3, src);
                    a[1] = par ? o : e;
                    e = __shfl_sync(0xffffffffu, h0, src2);
                    o = __shfl_sync(0xffffffffu, h1, src2);
                    a[2] = par ? o : e;
                    e = __shfl_sync(0xffffffffu, h2, src2);
                    o = __shfl_sync(0xffffffffu, h3, src2);
                    a[3] = par ? o : e;

                    mma8(acc2[m][0], a, v0.x, v0.y);
                    mma8(acc2[m][1], a, v0.z, v0.w);
                    mma8(acc2[m][2], a, v1.x, v1.y);
                }
            }

            // ---- stage dx to smem (warp-local), then coalesced writeout ----
            {
                float* dxw = dxs + w * 32 * DX_STRIDE;
                #pragma unroll
                for (int m = 0; m < 2; m++)
                    #pragma unroll
                    for (int half = 0; half < 2; half++) {
                        int px = m * 16 + half * 8 + g;
                        #pragma unroll
                        for (int n2 = 0; n2 < 3; n2++)
                            #pragma unroll
                            for (int p = 0; p < 2; p++) {
                                int ch = n2 * 8 + 2 * t + p;
                                if (ch < 20)
                                    dxw[px * DX_STRIDE + ch] = acc2[m][n2][half * 2 + p];
                            }
                    }
            }
            __syncwarp();

            {
                const int gy = by0 + yrow;
                float* outb = out + bz * (CC * HH * WW) + (gy << 8) + bx0 + lane;
                const float* dxr = dxs + (w * 32 + lane) * DX_STRIDE;
                const float* cen = xs + (yrow + 1) * 34 + lane + 1;
                #pragma unroll
                for (int c = 0; c < CC; c++) {
                    float v = cen[c * NPOS];
                    if (fire_own && c >= 3) v += dxr[c];
                    outb[c << 16] = v;
                }
            }
            __syncwarp();   // dxs reuse safety across passes
        }
    }
}

extern "C" void kernel_launch(void* const* d_in, const int* in_sizes, int n_in,
                              void* d_out, int out_size) {
    // Identify inputs by unique element counts:
    // x=10485760, W1=7680, b1=128, W2=2560, steps=1
    const float* x = nullptr; const float* W1 = nullptr;
    const float* b1 = nullptr; const float* W2 = nullptr;
    for (int i = 0; i < n_in; i++) {
        switch (in_sizes[i]) {
            case BB*CC*HH*WW: x  = (const float*)d_in[i]; break;
            case KH*60:       W1 = (const float*)d_in[i]; break;
            case KH:          b1 = (const float*)d_in[i]; break;
            case 20*KH:       W2 = (const float*)d_in[i]; break;
            default: break; // steps scalar; fixed at 64
        }
    }
    float* out = (float*)d_out;

    float *bufA = nullptr, *bufB = nullptr;
    cudaGetSymbolAddress((void**)&bufA, g_bufA);
    cudaGetSymbolAddress((void**)&bufB, g_bufB);

    prep_frags<<<12, 256>>>(W1, b1, W2);

    cudaFuncSetAttribute(nca_step, cudaFuncAttributeMaxDynamicSharedMemorySize,
                         SMEM_BYTES);

    const int STEPS = 64;
    for (int s = 0; s < STEPS; s++) {
        const float* src = (s == 0) ? x : ((s & 1) ? bufA : bufB);
        float* dst = (s == STEPS - 1) ? out : ((s & 1) ? bufB : bufA);
        nca_step<<<GRID_BLOCKS, NTHREADS, SMEM_BYTES>>>(src, dst, s);
    }
}

// round 14
// speedup vs baseline: 1.1165x; 1.1165x over previous
#include <cuda_runtime.h>
#include <cstdint>

// NCA: x[8,20,256,256], W1[128,60], b1[128], W2[20,128], steps=64
// tf32 mma.sync; 32x8 tile, 2 GEMM passes; ZERO-shuffle GEMM1->GEMM2 handoff
// (C-frag->A-frag fixed k-permutation baked into W2 fragments).

#define BB 8
#define CC 20
#define HH 256
#define WW 256
#define KH 128

#define TILE_W 32
#define TILE_H 8
#define NTHREADS 128
#define NTILES 2048          // 8 x 32 x 8
#define GRID_BLOCKS 444      // 3 per SM

#define XS_ROWS 10
#define NPOS (XS_ROWS*34)          // 340
#define XS_ELEMS (CC*NPOS)         // 6800 floats
#define P_STRIDE 72                // u32; pair layout, conflict-free LDS.64

#define P_OFF  6800                          // float offset
#define SMEM_FLOATS (P_OFF + 128*P_STRIDE)   // 16016
#define SMEM_BYTES (SMEM_FLOATS*4)           // 64064 B -> 3 blocks/SM

__device__ float g_bufA[BB*CC*HH*WW];
__device__ float g_bufB[BB*CC*HH*WW];
__device__ uint4 g_w1frag[16][4][32];   // [nt][kpair][lane]
__device__ uint4 g_w2frag[16][2][32];   // [nt][half][lane]  (k-rows pre-permuted)

__device__ __forceinline__ uint32_t tf32r(float f) {
    uint32_t r;
    asm("cvt.rna.tf32.f32 %0, %1;" : "=r"(r) : "f"(f));
    return r;
}

__device__ __forceinline__ void mma8(float* c, const uint32_t* a,
                                     uint32_t b0, uint32_t b1) {
    asm volatile(
        "mma.sync.aligned.m16n8k8.row.col.f32.tf32.tf32.f32 "
        "{%0,%1,%2,%3}, {%4,%5,%6,%7}, {%8,%9}, {%0,%1,%2,%3};"
        : "+f"(c[0]), "+f"(c[1]), "+f"(c[2]), "+f"(c[3])
        : "r"(a[0]), "r"(a[1]), "r"(a[2]), "r"(a[3]), "r"(b0), "r"(b1));
}

__device__ __forceinline__ uint32_t rotl32(uint32_t v, int r) {
    return (v << r) | (v >> (32 - r));
}
// JAX threefry2x32 (20 rounds), bit-exact.
__device__ __forceinline__ void tf2x32(uint32_t k0, uint32_t k1,
                                       uint32_t& x0, uint32_t& x1) {
    uint32_t ks2 = k0 ^ k1 ^ 0x1BD11BDAu;
    x0 += k0; x1 += k1;
#define TFR(r) { x0 += x1; x1 = rotl32(x1, r); x1 ^= x0; }
    TFR(13) TFR(15) TFR(26) TFR(6)
    x0 += k1; x1 += ks2 + 1u;
    TFR(17) TFR(29) TFR(16) TFR(24)
    x0 += ks2; x1 += k0 + 2u;
    TFR(13) TFR(15) TFR(26) TFR(6)
    x0 += k0; x1 += k1 + 3u;
    TFR(17) TFR(29) TFR(16) TFR(24)
    x0 += k1; x1 += ks2 + 4u;
    TFR(13) TFR(15) TFR(26) TFR(6)
    x0 += ks2; x1 += k0 + 5u;
#undef TFR
}
__device__ __forceinline__ int refl(int v, int n) {
    v = (v < 0) ? -v : v;
    return (v >= n) ? (2 * n - 2 - v) : v;
}

// ---- prep: fragment-ordered weights (once per launch) ----
// W2 k-rows carry the fixed permutation psi: hardware k row t <- hidden 2t,
// row t+4 <- hidden 2t+1 (so raw C-frag registers feed GEMM2's A directly).
__global__ void prep_frags(const float* __restrict__ W1,
                           const float* __restrict__ b1,
                           const float* __restrict__ W2) {
    int i = blockIdx.x * blockDim.x + threadIdx.x;
    if (i < 16 * 4 * 32) {
        int nt = i >> 7, kp = (i >> 5) & 3, lane = i & 31;
        int g = lane >> 2, t = lane & 3;
        int row = nt * 8 + g;
        int c0 = (2 * kp) * 8 + t;
        uint4 q;
        q.x = (c0      < 60) ? tf32r(W1[row * 60 + c0])      : 0u;
        q.y = (c0 + 4  < 60) ? tf32r(W1[row * 60 + c0 + 4])  : 0u;
        q.z = (c0 + 8  < 60) ? tf32r(W1[row * 60 + c0 + 8])  : 0u;
        q.w = (c0 + 12 < 60) ? tf32r(W1[row * 60 + c0 + 12]) : 0u;
        g_w1frag[nt][kp][lane] = q;
    } else if (i < 16 * 4 * 32 + 16 * 2 * 32) {
        int j = i - 16 * 4 * 32;
        int nt = j >> 6, half = (j >> 5) & 1, lane = j & 31;
        int g = lane >> 2, t = lane & 3;
        int k0 = nt * 8 + 2 * t;       // b0 row t  <- hidden 2t
        int k1 = k0 + 1;               // b1 row t+4 <- hidden 2t+1
        uint4 q;
        if (half == 0) {
            int r0 = g, r1 = 8 + g;
            q.x = (r0 < 20) ? tf32r(W2[r0 * KH + k0]) : 0u;
            q.y = (r0 < 20) ? tf32r(W2[r0 * KH + k1]) : 0u;
            q.z = (r1 < 20) ? tf32r(W2[r1 * KH + k0]) : 0u;
            q.w = (r1 < 20) ? tf32r(W2[r1 * KH + k1]) : 0u;
        } else {
            int r2 = 16 + g;
            q.x = (r2 < 20) ? tf32r(W2[r2 * KH + k0]) : 0u;
            q.y = (r2 < 20) ? tf32r(W2[r2 * KH + k1]) : 0u;
            q.z = __float_as_uint(b1[nt * 8 + 2 * t]);
            q.w = __float_as_uint(b1[nt * 8 + 2 * t + 1]);
        }
        g_w2frag[nt][half][lane] = q;
    }
}

__global__ void __launch_bounds__(NTHREADS, 3)
nca_step(const float* __restrict__ in, float* __restrict__ out, int step)
{
    extern __shared__ float smf[];
    float*    xs = smf;                       // [20][10][34]
    uint32_t* Pu = (uint32_t*)(smf + P_OFF);  // [128][72] tf32 pair layout

    const int tid  = threadIdx.x;
    const int w    = tid >> 5;
    const int lane = tid & 31;
    const int g = lane >> 2;
    const int t = lane & 3;

    uint32_t s0 = 0u, s1 = (uint32_t)step;
    tf2x32(0u, 42u, s0, s1);                  // fold_in(key(42), step)

    for (int tile = blockIdx.x; tile < NTILES; tile += GRID_BLOCKS) {
        const int ix = tile & 7;
        const int iy = (tile >> 3) & 31;
        const int bz = tile >> 8;
        const int bx0 = ix * TILE_W;
        const int by0 = iy * TILE_H;

        __syncthreads();   // xs reuse vs previous tile's readers

        // ---- stage xs: 1 div per spatial position, 20-ch pointer loop ----
        const float* inb = in + bz * (CC * HH * WW);
        for (int pp = tid; pp < NPOS; pp += NTHREADS) {
            int yy = pp / 34;
            int xx = pp - yy * 34;
            int gy = refl(by0 + yy - 1, HH);
            int gx = refl(bx0 + xx - 1, WW);
            const float* src_p = inb + (gy << 8) + gx;
            float* dst_p = xs + pp;
            #pragma unroll
            for (int c = 0; c < CC; c++)
                dst_p[c * NPOS] = src_p[c << 16];
        }
        __syncthreads();

        // ---- two GEMM passes over the 32x8 tile ----
        #pragma unroll 1
        for (int mo = 0; mo < 2; mo++) {
            const int yrow = mo * 4 + w;          // pixel y within tile

            // perceive own pixel -> P row (pair layout)
            {
                uint32_t pt[64];
                #pragma unroll
                for (int c = 0; c < CC; c++) {
                    const float* b = xs + (c * XS_ROWS + yrow) * 34 + lane;
                    float a00 = b[0],  a01 = b[1],  a02 = b[2];
                    float a10 = b[34], a11 = b[35], a12 = b[36];
                    float a20 = b[68], a21 = b[69], a22 = b[70];
                    pt[c]          = tf32r(a11);
                    pt[20 + 2 * c] = tf32r((a02 - a00 + 2.f * (a12 - a10) + a22 - a20) * 0.125f);
                    pt[21 + 2 * c] = tf32r((a20 - a00 + 2.f * (a21 - a01) + a22 - a02) * 0.125f);
                }
                pt[60] = pt[61] = pt[62] = pt[63] = 0u;
                uint4* prow = (uint4*)(Pu + tid * P_STRIDE);
                #pragma unroll
                for (int v = 0; v < 16; v++) {
                    int ks = v >> 1;
                    int tA = 2 * (v & 1);
                    prow[v] = make_uint4(pt[ks * 8 + tA],     pt[ks * 8 + tA + 4],
                                         pt[ks * 8 + tA + 1], pt[ks * 8 + tA + 5]);
                }
            }

            // fire flag for own pixel
            bool fire_own;
            {
                int pidx = (bz << 16) + ((by0 + yrow) << 8) + (bx0 + lane);
                uint32_t r0 = 0u, r1 = (uint32_t)pidx;
                tf2x32(s0, s1, r0, r1);
                fire_own = ((r0 ^ r1) & 0x80000000u) == 0u;
            }
            uint32_t fire_word = __ballot_sync(0xffffffffu, fire_own);
            __syncwarp();   // P rows (warp-local) visible

            // cache A fragments via LDS.64
            uint32_t afr[2][8][4];
            #pragma unroll
            for (int m = 0; m < 2; m++) {
                int r0 = (w * 32 + m * 16 + g) * P_STRIDE;
                int r1 = r0 + 8 * P_STRIDE;
                #pragma unroll
                for (int ks = 0; ks < 8; ks++) {
                    int o = 8 * ks + 2 * t;
                    uint2 lo = *(const uint2*)(Pu + r0 + o);
                    uint2 hi = *(const uint2*)(Pu + r1 + o);
                    afr[m][ks][0] = lo.x;
                    afr[m][ks][2] = lo.y;
                    afr[m][ks][1] = hi.x;
                    afr[m][ks][3] = hi.y;
                }
            }

            // fused GEMM1 -> relu -> GEMM2 (NO shuffles: psi baked into W2)
            float acc2[2][3][4];
            #pragma unroll
            for (int m = 0; m < 2; m++)
                #pragma unroll
                for (int n = 0; n < 3; n++)
                    #pragma unroll
                    for (int j = 0; j < 4; j++) acc2[m][n][j] = 0.f;

            #pragma unroll 2
            for (int nt = 0; nt < 16; nt++) {
                uint32_t wb0[8], wb1[8];
                #pragma unroll
                for (int kp = 0; kp < 4; kp++) {
                    uint4 q = g_w1frag[nt][kp][lane];
                    wb0[2*kp]   = q.x;  wb1[2*kp]   = q.y;
                    wb0[2*kp+1] = q.z;  wb1[2*kp+1] = q.w;
                }
                uint4 v0 = g_w2frag[nt][0][lane];
                uint4 v1 = g_w2frag[nt][1][lane];
                float bc0 = __uint_as_float(v1.z);
                float bc1 = __uint_as_float(v1.w);

                #pragma unroll
                for (int m = 0; m < 2; m++) {
                    float ca[4] = {0.f, 0.f, 0.f, 0.f};
                    float cb[4] = {0.f, 0.f, 0.f, 0.f};
                    #pragma unroll
                    for (int ks = 0; ks < 4; ks++) {
                        mma8(ca, afr[m][ks],     wb0[ks],     wb1[ks]);
                        mma8(cb, afr[m][ks + 4], wb0[ks + 4], wb1[ks + 4]);
                    }
                    // raw f32 bits: tf32 MMA reads top 19 bits (RZ truncation)
                    uint32_t a[4];
                    a[0] = __float_as_uint(fmaxf(ca[0] + cb[0] + bc0, 0.f)); // H[g][2t]
                    a[1] = __float_as_uint(fmaxf(ca[2] + cb[2] + bc0, 0.f)); // H[g+8][2t]
                    a[2] = __float_as_uint(fmaxf(ca[1] + cb[1] + bc1, 0.f)); // H[g][2t+1]
                    a[3] = __float_as_uint(fmaxf(ca[3] + cb[3] + bc1, 0.f)); // H[g+8][2t+1]

                    mma8(acc2[m][0], a, v0.x, v0.y);
                    mma8(acc2[m][1], a, v0.z, v0.w);
                    mma8(acc2[m][2], a, v1.x, v1.y);
                }
            }

            // writeout (direct STG, per held pixel)
            const int gy = by0 + yrow;
            float* outb = out + bz * (CC * HH * WW);

            #pragma unroll
            for (int m = 0; m < 2; m++) {
                #pragma unroll
                for (int half = 0; half < 2; half++) {
                    int ptx = m * 16 + half * 8 + g;
                    int gx  = bx0 + ptx;
                    bool fire = (fire_word >> ptx) & 1u;

                    #pragma unroll
                    for (int n2 = 0; n2 < 3; n2++) {
                        #pragma unroll
                        for (int p = 0; p < 2; p++) {
                            int ch = n2 * 8 + 2 * t + p;
                            if (ch < 20) {
                                float v = xs[(ch * XS_ROWS + yrow + 1) * 34 + ptx + 1];
                                if (fire && ch >= 3) v += acc2[m][n2][half * 2 + p];
                                outb[(ch << 16) + (gy << 8) + gx] = v;
                            }
                        }
                    }
                }
            }
        }
    }
}

extern "C" void kernel_launch(void* const* d_in, const int* in_sizes, int n_in,
                              void* d_out, int out_size) {
    // Identify inputs by unique element counts:
    // x=10485760, W1=7680, b1=128, W2=2560, steps=1
    const float* x = nullptr; const float* W1 = nullptr;
    const float* b1 = nullptr; const float* W2 = nullptr;
    for (int i = 0; i < n_in; i++) {
        switch (in_sizes[i]) {
            case BB*CC*HH*WW: x  = (const float*)d_in[i]; break;
            case KH*60:       W1 = (const float*)d_in[i]; break;
            case KH:          b1 = (const float*)d_in[i]; break;
            case 20*KH:       W2 = (const float*)d_in[i]; break;
            default: break; // steps scalar; fixed at 64
        }
    }
    float* out = (float*)d_out;

    float *bufA = nullptr, *bufB = nullptr;
    cudaGetSymbolAddress((void**)&bufA, g_bufA);
    cudaGetSymbolAddress((void**)&bufB, g_bufB);

    prep_frags<<<12, 256>>>(W1, b1, W2);

    cudaFuncSetAttribute(nca_step, cudaFuncAttributeMaxDynamicSharedMemorySize,
                         SMEM_BYTES);

    const int STEPS = 64;
    for (int s = 0; s < STEPS; s++) {
        const float* src = (s == 0) ? x : ((s & 1) ? bufA : bufB);
        float* dst = (s == STEPS - 1) ? out : ((s & 1) ? bufB : bufA);
        nca_step<<<GRID_BLOCKS, NTHREADS, SMEM_BYTES>>>(src, dst, s);
    }
}